// round 11
// baseline (speedup 1.0000x reference)
#include <cuda_runtime.h>
#include <cuda_fp16.h>
#include <math.h>

// Problem constants
#define BB 2
#define DD 160
#define HH 160
#define WW 160
#define SLICE (HH*WW)          // 25600
#define VOL (DD*SLICE)         // 4096000
#define TOTAL (BB*VOL)         // 8192000
#define RAD 5
#define WIN 11

#define TH 16                  // h-rows per tile in kernel 1
#define HR (TH + 2*RAD)        // 26 rows incl halo
#define SF2 161                // slab stride in float2 units (odd -> conflict-free)
#define SPU 161                // product plane stride in uint(half2) units (odd)
#define NTILE (HH/TH)          // 10
#define NBLK1 (NTILE*DD*BB)    // 3200 blocks in kernel 1

#define NSEG 8                 // w-segments in stage 2
#define SEGW (WW/NSEG)         // 20

#define NSPLIT 8
#define DR (DD/NSPLIT)         // 20 d-steps per thread in kernel 2
#define NCOLS (BB*SLICE)       // 51200 columns
#define TPB2 256
#define NTH2 ((NCOLS/4)*NSPLIT)     // 102400 threads in kernel 2
#define NBLK2 (NTH2/TPB2)           // 400 blocks

// SSIM constants in raw-sum space (multiplied through by 1331^4)
#define C1S 1.0559354e-3f           // 0.01/4096^2 * 1331^2
#define C2S 3.1678061e-3f           // 0.03/4096^2 * 1331^2
#define EPSS 31384.2838f            // 1e-8 * 1331^4

// Global scratch: pair-interleaved half2 fields.
// g_pair[0][v] = half2(Sx, Sy) ; g_pair[1][v] = half2(Sq, Sxy)
__device__ __align__(16) unsigned int g_pair[2][TOTAL];
__device__ float g_l1p[NBLK1];
__device__ float g_ssimp[NBLK2];

__device__ __forceinline__ unsigned int pack2(float a, float b)
{
    __half2 h = __floats2half2_rn(a, b);
    return *reinterpret_cast<unsigned int*>(&h);
}
__device__ __forceinline__ float2 unpack2(unsigned int u)
{
    __half2 h = *reinterpret_cast<__half2*>(&u);
    return __half22float2(h);
}

// ---------------------------------------------------------------------------
// Kernel 1: per (b,d,h-tile): products + sliding W-sum + sliding H-sum.
// float2-interleaved slab, half2-packed product planes, uint2 global stores.
// ---------------------------------------------------------------------------
__global__ void __launch_bounds__(256, 3) wh_kernel(const float* __restrict__ x,
                                                    const float* __restrict__ y)
{
    extern __shared__ float sm[];
    float2* slab = (float2*)sm;                         // HR*SF2 float2
    unsigned int* sp = (unsigned int*)(sm + 2*HR*SF2);  // 2 planes * HR * SPU
    __shared__ float red[256];

    const int tid = threadIdx.x;
    const int th  = blockIdx.x;             // 0..NTILE-1
    const int d   = blockIdx.y;             // 0..159
    const int b   = blockIdx.z;             // 0..1
    const int h0  = th * TH;
    const size_t base = ((size_t)b*DD + d) * SLICE;

    // ---- Stage 1: vectorized halo'd slab load + fused smooth-L1 on owned rows
    float l1acc = 0.f;
    const int W4 = WW/4;                    // 40
    for (int idx = tid; idx < HR*W4; idx += 256) {
        int r  = idx / W4;
        int w4 = idx - r*W4;
        int gh = h0 - RAD + r;
        float4 xv = make_float4(0.f,0.f,0.f,0.f);
        float4 yv = make_float4(0.f,0.f,0.f,0.f);
        if (gh >= 0 && gh < HH) {
            size_t g = (base + (size_t)gh*WW + w4*4) >> 2;
            xv = ((const float4*)x)[g];
            yv = ((const float4*)y)[g];
        }
        float2* row = slab + r*SF2 + w4*4;
        row[0] = make_float2(xv.x, yv.x);
        row[1] = make_float2(xv.y, yv.y);
        row[2] = make_float2(xv.z, yv.z);
        row[3] = make_float2(xv.w, yv.w);
        if (r >= RAD && r < RAD + TH) {
            float d0=fabsf(xv.x-yv.x), d1=fabsf(xv.y-yv.y);
            float d2=fabsf(xv.z-yv.z), d3=fabsf(xv.w-yv.w);
            l1acc += (d0<1.f)?0.5f*d0*d0:(d0-0.5f);
            l1acc += (d1<1.f)?0.5f*d1*d1:(d1-0.5f);
            l1acc += (d2<1.f)?0.5f*d2*d2:(d2-0.5f);
            l1acc += (d3<1.f)?0.5f*d3*d3:(d3-0.5f);
        }
    }
    __syncthreads();

    // ---- Stage 2: sliding W-sum, register ring, half2-packed STS
    if (tid < NSEG*HR) {
        int s = tid / HR;               // w-segment
        int r = tid - s*HR;             // row 0..HR-1
        int w0 = s * SEGW;
        const float2* row = slab + r*SF2;
        float2 ring[WIN];
        float a0=0.f, a1=0.f, a2=0.f, a3=0.f;
        #pragma unroll
        for (int i = 0; i < WIN; i++) {
            int t = w0 - RAD + i;
            float2 v = make_float2(0.f, 0.f);
            if (t >= 0) v = row[t];            // t < WW always
            ring[i] = v;
            a0 += v.x; a1 += v.y; a2 += v.x*v.x + v.y*v.y; a3 += v.x*v.y;
        }
        unsigned int* q0 = sp + r*SPU;
        unsigned int* q1 = sp + HR*SPU + r*SPU;
        #pragma unroll
        for (int k = 0; k < SEGW; k++) {
            int w = w0 + k;
            q0[w] = pack2(a0, a1);
            q1[w] = pack2(a2, a3);
            float2 o = ring[k%WIN];
            a0 -= o.x; a1 -= o.y; a2 -= o.x*o.x + o.y*o.y; a3 -= o.x*o.y;
            int tin = w + RAD + 1;
            float2 v = make_float2(0.f, 0.f);
            if (tin < WW) v = row[tin];
            ring[k%WIN] = v;
            a0 += v.x; a1 += v.y; a2 += v.x*v.x + v.y*v.y; a3 += v.x*v.y;
        }
    }
    __syncthreads();

    // ---- Stage 3: sliding H-sum; job = (plane, pair of adjacent w)
    if (tid < 2*(WW/2)) {               // 160 jobs
        int fp = tid / (WW/2);          // plane 0..1
        int w2 = tid - fp*(WW/2);       // 0..79
        const unsigned int* colb = sp + fp*(HR*SPU) + 2*w2;
        float4 ring[WIN];
        float a0=0.f, a1=0.f, a2=0.f, a3=0.f;
        #pragma unroll
        for (int i = 0; i < WIN; i++) {
            float2 pa = unpack2(colb[i*SPU]);
            float2 pb = unpack2(colb[i*SPU + 1]);
            ring[i] = make_float4(pa.x, pa.y, pb.x, pb.y);
            a0 += pa.x; a1 += pa.y; a2 += pb.x; a3 += pb.y;
        }
        unsigned int* gout = g_pair[fp] + base + (size_t)h0*WW + 2*w2;
        #pragma unroll
        for (int ro = 0; ro < TH; ro++) {
            uint2 o;
            o.x = pack2(a0, a1);
            o.y = pack2(a2, a3);
            *reinterpret_cast<uint2*>(gout + (size_t)ro*WW) = o;
            if (ro < TH - 1) {
                float2 pa = unpack2(colb[(ro + WIN)*SPU]);
                float2 pb = unpack2(colb[(ro + WIN)*SPU + 1]);
                float4 og = ring[ro%WIN];
                a0 += pa.x - og.x; a1 += pa.y - og.y;
                a2 += pb.x - og.z; a3 += pb.y - og.w;
                ring[ro%WIN] = make_float4(pa.x, pa.y, pb.x, pb.y);
            }
        }
    }

    // ---- L1 block reduce
    red[tid] = l1acc;
    __syncthreads();
    for (int s2 = 128; s2 > 0; s2 >>= 1) {
        if (tid < s2) red[tid] += red[tid + s2];
        __syncthreads();
    }
    if (tid == 0) {
        int bid = blockIdx.x + NTILE*(blockIdx.y + DD*blockIdx.z);
        g_l1p[bid] = red[0];
    }
}

// ---------------------------------------------------------------------------
// Kernel 2: sliding D-sum over 4 columns/thread via 2 uint4 loads per step.
// ---------------------------------------------------------------------------
__device__ __forceinline__ float ssim_elem(float Sx, float Sy, float Sq, float Sxy)
{
    float q  = 2.f * Sx * Sy;
    float T  = Sx*Sx + Sy*Sy;
    float N1 = q + C1S;
    float N2 = fmaf(2662.f, Sxy, C2S - q);
    float D1 = T + C1S;
    float D2 = fmaf(1331.f, Sq, C2S - T);
    float ss = __fdividef(N1*N2, fmaf(D1, D2, EPSS));
    float v  = 0.5f - 0.5f*ss;
    return fminf(fmaxf(v, 0.f), 1.f);
}

__device__ __forceinline__ void accum(const uint4 p, const uint4 q,
                                      float* Sx, float* Sy, float* Sq, float* Sxy,
                                      float sgn)
{
    float2 v;
    v = unpack2(p.x); Sx[0] += sgn*v.x; Sy[0] += sgn*v.y;
    v = unpack2(p.y); Sx[1] += sgn*v.x; Sy[1] += sgn*v.y;
    v = unpack2(p.z); Sx[2] += sgn*v.x; Sy[2] += sgn*v.y;
    v = unpack2(p.w); Sx[3] += sgn*v.x; Sy[3] += sgn*v.y;
    v = unpack2(q.x); Sq[0] += sgn*v.x; Sxy[0] += sgn*v.y;
    v = unpack2(q.y); Sq[1] += sgn*v.x; Sxy[1] += sgn*v.y;
    v = unpack2(q.z); Sq[2] += sgn*v.x; Sxy[2] += sgn*v.y;
    v = unpack2(q.w); Sq[3] += sgn*v.x; Sxy[3] += sgn*v.y;
}

__global__ void __launch_bounds__(TPB2) dpass_kernel()
{
    const int gid   = blockIdx.x * TPB2 + threadIdx.x;   // 0..NTH2-1
    const int QC    = NCOLS/4;                           // 12800
    const int split = gid / QC;
    const int c4    = gid - split*QC;
    const int col   = c4 * 4;
    const int b     = col / SLICE;
    const int hw    = col - b*SLICE;
    const size_t b4 = ((size_t)b*VOL + hw) >> 2;         // uint4 index
    const int S4 = SLICE/4;                              // 6400

    const uint4* __restrict__ P0 = (const uint4*)g_pair[0] + b4;
    const uint4* __restrict__ P1 = (const uint4*)g_pair[1] + b4;

    float Sx[4]  = {0,0,0,0};
    float Sy[4]  = {0,0,0,0};
    float Sq[4]  = {0,0,0,0};
    float Sxy[4] = {0,0,0,0};

    const int d0 = split * DR;
    int tlo = d0 - RAD; if (tlo < 0) tlo = 0;
    for (int t = tlo; t <= d0 + RAD; t++) {
        size_t o = (size_t)t * S4;
        accum(P0[o], P1[o], Sx, Sy, Sq, Sxy, 1.f);
    }

    float acc = 0.f;
    if (split != 0 && split != NSPLIT-1) {
        // interior: no d-boundary checks -> unconditional loads, unrollable
        #pragma unroll 4
        for (int d = d0; d < d0 + DR; d++) {
            #pragma unroll
            for (int i = 0; i < 4; i++)
                acc += ssim_elem(Sx[i], Sy[i], Sq[i], Sxy[i]);
            size_t oi = (size_t)(d + RAD + 1) * S4;
            size_t oo = (size_t)(d - RAD) * S4;
            accum(P0[oi], P1[oi], Sx, Sy, Sq, Sxy,  1.f);
            accum(P0[oo], P1[oo], Sx, Sy, Sq, Sxy, -1.f);
        }
    } else {
        for (int d = d0; d < d0 + DR; d++) {
            #pragma unroll
            for (int i = 0; i < 4; i++)
                acc += ssim_elem(Sx[i], Sy[i], Sq[i], Sxy[i]);
            if (d < d0 + DR - 1) {
                int tin  = d + RAD + 1;
                int tout = d - RAD;
                if (tin < DD) {
                    size_t o = (size_t)tin * S4;
                    accum(P0[o], P1[o], Sx, Sy, Sq, Sxy, 1.f);
                }
                if (tout >= 0) {
                    size_t o = (size_t)tout * S4;
                    accum(P0[o], P1[o], Sx, Sy, Sq, Sxy, -1.f);
                }
            }
        }
    }

    __shared__ float red[TPB2];
    red[threadIdx.x] = acc;
    __syncthreads();
    for (int s2 = TPB2/2; s2 > 0; s2 >>= 1) {
        if (threadIdx.x < s2) red[threadIdx.x] += red[threadIdx.x + s2];
        __syncthreads();
    }
    if (threadIdx.x == 0) g_ssimp[blockIdx.x] = red[0];
}

// ---------------------------------------------------------------------------
// Kernel 3: finalize in double precision.
// ---------------------------------------------------------------------------
__global__ void finalize_kernel(float* __restrict__ out)
{
    __shared__ double red[256];
    const int tid = threadIdx.x;

    double a = 0.0;
    for (int i = tid; i < NBLK1; i += 256) a += (double)g_l1p[i];
    red[tid] = a; __syncthreads();
    for (int s = 128; s > 0; s >>= 1) {
        if (tid < s) red[tid] += red[tid + s];
        __syncthreads();
    }
    double l1sum = red[0];
    __syncthreads();

    double c = 0.0;
    for (int i = tid; i < NBLK2; i += 256) c += (double)g_ssimp[i];
    red[tid] = c; __syncthreads();
    for (int s = 128; s > 0; s >>= 1) {
        if (tid < s) red[tid] += red[tid + s];
        __syncthreads();
    }
    if (tid == 0) {
        double ssim_mean = red[0] / (double)TOTAL;
        double l1_mean   = l1sum  / (double)TOTAL;
        out[0] = (float)(0.85 * ssim_mean + 0.15 * l1_mean);
    }
}

// ---------------------------------------------------------------------------
extern "C" void kernel_launch(void* const* d_in, const int* in_sizes, int n_in,
                              void* d_out, int out_size)
{
    const float* pred   = (const float*)d_in[0];
    const float* target = (const float*)d_in[1];
    float* out = (float*)d_out;

    // dynamic smem: float2 slab + 2 half2 product planes
    const int smem_bytes = HR*SF2*(int)sizeof(float2) + 2*HR*SPU*(int)sizeof(unsigned int); // 66,976 B
    cudaFuncSetAttribute(wh_kernel, cudaFuncAttributeMaxDynamicSharedMemorySize, smem_bytes);

    dim3 g1(NTILE, DD, BB);   // 3200 blocks
    wh_kernel<<<g1, 256, smem_bytes>>>(pred, target);
    dpass_kernel<<<NBLK2, TPB2>>>();
    finalize_kernel<<<1, 256>>>(out);
}

// round 12
// speedup vs baseline: 1.1165x; 1.1165x over previous
#include <cuda_runtime.h>
#include <cuda_fp16.h>
#include <math.h>

// Problem constants
#define BB 2
#define DD 160
#define HH 160
#define WW 160
#define SLICE (HH*WW)          // 25600
#define VOL (DD*SLICE)         // 4096000
#define TOTAL (BB*VOL)         // 8192000
#define RAD 5
#define WIN 11

#define TH 16                  // h-rows per tile in kernel 1
#define HR (TH + 2*RAD)        // 26 rows incl halo
#define SH 161                 // slab stride in half2 units (odd -> conflict-free)
#define SP2 161                // product stride in uint2 units
#define NTILE (HH/TH)          // 10
#define NBLK1 (NTILE*DD*BB)    // 3200 blocks in kernel 1

#define NSEG 8                 // w-segments in stage 2
#define SEGW (WW/NSEG)         // 20

#define NSPLIT 16
#define DR (DD/NSPLIT)         // 10 d-steps per thread in kernel 2
#define NCOLS (BB*SLICE)       // 51200 columns
#define TPB2 256
#define NTH2 ((NCOLS/4)*NSPLIT)     // 204800 threads in kernel 2
#define NBLK2 (NTH2/TPB2)           // 800 blocks

// SSIM constants in raw-sum space (multiplied through by 1331^4)
#define C1S 1.0559354e-3f           // 0.01/4096^2 * 1331^2
#define C2S 3.1678061e-3f           // 0.03/4096^2 * 1331^2
#define EPSS 31384.2838f            // 1e-8 * 1331^4

// Global scratch: fully interleaved per-voxel uint2:
//   .x = half2(Sx, Sy) ; .y = half2(Sq, Sxy)
__device__ __align__(16) uint2 g_all[TOTAL];
__device__ float g_l1p[NBLK1];
__device__ float g_ssimp[NBLK2];

__device__ __forceinline__ unsigned int pack2(float a, float b)
{
    __half2 h = __floats2half2_rn(a, b);
    return *reinterpret_cast<unsigned int*>(&h);
}
__device__ __forceinline__ float2 unpack2(unsigned int u)
{
    __half2 h = *reinterpret_cast<__half2*>(&u);
    return __half22float2(h);
}

// ---------------------------------------------------------------------------
// Kernel 1: per (b,d,h-tile): products + sliding W-sum + sliding H-sum.
// fp16 (x,y)-packed slab, interleaved uint2 product buffer + global field.
// ---------------------------------------------------------------------------
__global__ void __launch_bounds__(256, 4) wh_kernel(const float* __restrict__ x,
                                                    const float* __restrict__ y)
{
    extern __shared__ float sm[];
    unsigned int* slab = (unsigned int*)sm;              // HR*SH half2 (as uint)
    uint2* sp = (uint2*)(slab + HR*SH);                  // HR*SP2 uint2
    __shared__ float red[256];

    const int tid = threadIdx.x;
    const int th  = blockIdx.x;             // 0..NTILE-1
    const int d   = blockIdx.y;             // 0..159
    const int b   = blockIdx.z;             // 0..1
    const int h0  = th * TH;
    const size_t base = ((size_t)b*DD + d) * SLICE;

    // ---- Stage 1: vectorized halo'd slab load + fused smooth-L1 on owned rows
    float l1acc = 0.f;
    const int W4 = WW/4;                    // 40
    for (int idx = tid; idx < HR*W4; idx += 256) {
        int r  = idx / W4;
        int w4 = idx - r*W4;
        int gh = h0 - RAD + r;
        float4 xv = make_float4(0.f,0.f,0.f,0.f);
        float4 yv = make_float4(0.f,0.f,0.f,0.f);
        if (gh >= 0 && gh < HH) {
            size_t g = (base + (size_t)gh*WW + w4*4) >> 2;
            xv = ((const float4*)x)[g];
            yv = ((const float4*)y)[g];
        }
        unsigned int* row = slab + r*SH + w4*4;
        row[0] = pack2(xv.x, yv.x);
        row[1] = pack2(xv.y, yv.y);
        row[2] = pack2(xv.z, yv.z);
        row[3] = pack2(xv.w, yv.w);
        if (r >= RAD && r < RAD + TH) {
            float d0=fabsf(xv.x-yv.x), d1=fabsf(xv.y-yv.y);
            float d2=fabsf(xv.z-yv.z), d3=fabsf(xv.w-yv.w);
            l1acc += (d0<1.f)?0.5f*d0*d0:(d0-0.5f);
            l1acc += (d1<1.f)?0.5f*d1*d1:(d1-0.5f);
            l1acc += (d2<1.f)?0.5f*d2*d2:(d2-0.5f);
            l1acc += (d3<1.f)?0.5f*d3*d3:(d3-0.5f);
        }
    }
    __syncthreads();

    // ---- Stage 2: sliding W-sum, raw half2 ring, interleaved STS.64
    if (tid < NSEG*HR) {
        int s = tid / HR;               // w-segment
        int r = tid - s*HR;             // row 0..HR-1
        int w0 = s * SEGW;
        const unsigned int* row = slab + r*SH;
        unsigned int ring[WIN];
        float a0=0.f, a1=0.f, a2=0.f, a3=0.f;
        #pragma unroll
        for (int i = 0; i < WIN; i++) {
            int t = w0 - RAD + i;
            unsigned int u = 0u;
            if (t >= 0) u = row[t];            // t < WW always
            ring[i] = u;
            float2 v = unpack2(u);
            a0 += v.x; a1 += v.y; a2 += v.x*v.x + v.y*v.y; a3 += v.x*v.y;
        }
        uint2* q = sp + r*SP2;
        #pragma unroll
        for (int k = 0; k < SEGW; k++) {
            int w = w0 + k;
            q[w] = make_uint2(pack2(a0, a1), pack2(a2, a3));
            float2 o = unpack2(ring[k%WIN]);
            a0 -= o.x; a1 -= o.y; a2 -= o.x*o.x + o.y*o.y; a3 -= o.x*o.y;
            int tin = w + RAD + 1;
            unsigned int u = 0u;
            if (tin < WW) u = row[tin];
            ring[k%WIN] = u;
            float2 v = unpack2(u);
            a0 += v.x; a1 += v.y; a2 += v.x*v.x + v.y*v.y; a3 += v.x*v.y;
        }
    }
    __syncthreads();

    // ---- Stage 3: sliding H-sum; one job per w column, LDS.64 per row
    if (tid < WW) {                      // 160 jobs
        const uint2* colb = sp + tid;
        uint2 ring[WIN];
        float a0=0.f, a1=0.f, a2=0.f, a3=0.f;
        #pragma unroll
        for (int i = 0; i < WIN; i++) {
            uint2 u = colb[i*SP2];
            ring[i] = u;
            float2 pa = unpack2(u.x);
            float2 pb = unpack2(u.y);
            a0 += pa.x; a1 += pa.y; a2 += pb.x; a3 += pb.y;
        }
        uint2* gout = g_all + base + (size_t)h0*WW + tid;
        #pragma unroll
        for (int ro = 0; ro < TH; ro++) {
            gout[(size_t)ro*WW] = make_uint2(pack2(a0, a1), pack2(a2, a3));
            if (ro < TH - 1) {
                uint2 u = colb[(ro + WIN)*SP2];
                float2 pa = unpack2(u.x);
                float2 pb = unpack2(u.y);
                float2 oa = unpack2(ring[ro%WIN].x);
                float2 ob = unpack2(ring[ro%WIN].y);
                a0 += pa.x - oa.x; a1 += pa.y - oa.y;
                a2 += pb.x - ob.x; a3 += pb.y - ob.y;
                ring[ro%WIN] = u;
            }
        }
    }

    // ---- L1 block reduce
    red[tid] = l1acc;
    __syncthreads();
    for (int s2 = 128; s2 > 0; s2 >>= 1) {
        if (tid < s2) red[tid] += red[tid + s2];
        __syncthreads();
    }
    if (tid == 0) {
        int bid = blockIdx.x + NTILE*(blockIdx.y + DD*blockIdx.z);
        g_l1p[bid] = red[0];
    }
}

// ---------------------------------------------------------------------------
// Kernel 2: sliding D-sum over 4 columns/thread via 2 uint4 loads per step.
// ---------------------------------------------------------------------------
__device__ __forceinline__ float ssim_elem(float Sx, float Sy, float Sq, float Sxy)
{
    float q  = 2.f * Sx * Sy;
    float T  = Sx*Sx + Sy*Sy;
    float N1 = q + C1S;
    float N2 = fmaf(2662.f, Sxy, C2S - q);
    float D1 = T + C1S;
    float D2 = fmaf(1331.f, Sq, C2S - T);
    float ss = __fdividef(N1*N2, fmaf(D1, D2, EPSS));
    float v  = 0.5f - 0.5f*ss;
    return fminf(fmaxf(v, 0.f), 1.f);
}

// U0 covers voxels {0,1}, U1 covers voxels {2,3} (interleaved uint2 layout)
__device__ __forceinline__ void accum(const uint4 U0, const uint4 U1,
                                      float* Sx, float* Sy, float* Sq, float* Sxy,
                                      float sgn)
{
    float2 v;
    v = unpack2(U0.x); Sx[0] += sgn*v.x; Sy[0]  += sgn*v.y;
    v = unpack2(U0.y); Sq[0] += sgn*v.x; Sxy[0] += sgn*v.y;
    v = unpack2(U0.z); Sx[1] += sgn*v.x; Sy[1]  += sgn*v.y;
    v = unpack2(U0.w); Sq[1] += sgn*v.x; Sxy[1] += sgn*v.y;
    v = unpack2(U1.x); Sx[2] += sgn*v.x; Sy[2]  += sgn*v.y;
    v = unpack2(U1.y); Sq[2] += sgn*v.x; Sxy[2] += sgn*v.y;
    v = unpack2(U1.z); Sx[3] += sgn*v.x; Sy[3]  += sgn*v.y;
    v = unpack2(U1.w); Sq[3] += sgn*v.x; Sxy[3] += sgn*v.y;
}

__global__ void __launch_bounds__(TPB2) dpass_kernel()
{
    const int gid   = blockIdx.x * TPB2 + threadIdx.x;   // 0..NTH2-1
    const int QC    = NCOLS/4;                           // 12800
    const int split = gid / QC;
    const int c4    = gid - split*QC;
    const int col   = c4 * 4;
    const int b     = col / SLICE;
    const int hw    = col - b*SLICE;
    const size_t b8 = ((size_t)b*VOL + hw) >> 1;         // uint4 index (2 voxels per uint4)
    const int S8 = SLICE/2;                              // 12800 uint4 per slice

    const uint4* __restrict__ G = (const uint4*)g_all + b8;

    float Sx[4]  = {0,0,0,0};
    float Sy[4]  = {0,0,0,0};
    float Sq[4]  = {0,0,0,0};
    float Sxy[4] = {0,0,0,0};

    const int d0 = split * DR;
    int tlo = d0 - RAD; if (tlo < 0) tlo = 0;
    for (int t = tlo; t <= d0 + RAD; t++) {
        size_t o = (size_t)t * S8;
        accum(G[o], G[o+1], Sx, Sy, Sq, Sxy, 1.f);
    }

    float acc = 0.f;
    if (split != 0 && split != NSPLIT-1) {
        // interior: no d-boundary checks -> unconditional loads, unrollable
        #pragma unroll
        for (int d = d0; d < d0 + DR; d++) {
            #pragma unroll
            for (int i = 0; i < 4; i++)
                acc += ssim_elem(Sx[i], Sy[i], Sq[i], Sxy[i]);
            size_t oi = (size_t)(d + RAD + 1) * S8;
            size_t oo = (size_t)(d - RAD) * S8;
            accum(G[oi], G[oi+1], Sx, Sy, Sq, Sxy,  1.f);
            accum(G[oo], G[oo+1], Sx, Sy, Sq, Sxy, -1.f);
        }
    } else {
        for (int d = d0; d < d0 + DR; d++) {
            #pragma unroll
            for (int i = 0; i < 4; i++)
                acc += ssim_elem(Sx[i], Sy[i], Sq[i], Sxy[i]);
            if (d < d0 + DR - 1) {
                int tin  = d + RAD + 1;
                int tout = d - RAD;
                if (tin < DD) {
                    size_t o = (size_t)tin * S8;
                    accum(G[o], G[o+1], Sx, Sy, Sq, Sxy, 1.f);
                }
                if (tout >= 0) {
                    size_t o = (size_t)tout * S8;
                    accum(G[o], G[o+1], Sx, Sy, Sq, Sxy, -1.f);
                }
            }
        }
    }

    __shared__ float red[TPB2];
    red[threadIdx.x] = acc;
    __syncthreads();
    for (int s2 = TPB2/2; s2 > 0; s2 >>= 1) {
        if (threadIdx.x < s2) red[threadIdx.x] += red[threadIdx.x + s2];
        __syncthreads();
    }
    if (threadIdx.x == 0) g_ssimp[blockIdx.x] = red[0];
}

// ---------------------------------------------------------------------------
// Kernel 3: finalize in double precision.
// ---------------------------------------------------------------------------
__global__ void finalize_kernel(float* __restrict__ out)
{
    __shared__ double red[256];
    const int tid = threadIdx.x;

    double a = 0.0;
    for (int i = tid; i < NBLK1; i += 256) a += (double)g_l1p[i];
    red[tid] = a; __syncthreads();
    for (int s = 128; s > 0; s >>= 1) {
        if (tid < s) red[tid] += red[tid + s];
        __syncthreads();
    }
    double l1sum = red[0];
    __syncthreads();

    double c = 0.0;
    for (int i = tid; i < NBLK2; i += 256) c += (double)g_ssimp[i];
    red[tid] = c; __syncthreads();
    for (int s = 128; s > 0; s >>= 1) {
        if (tid < s) red[tid] += red[tid + s];
        __syncthreads();
    }
    if (tid == 0) {
        double ssim_mean = red[0] / (double)TOTAL;
        double l1_mean   = l1sum  / (double)TOTAL;
        out[0] = (float)(0.85 * ssim_mean + 0.15 * l1_mean);
    }
}

// ---------------------------------------------------------------------------
extern "C" void kernel_launch(void* const* d_in, const int* in_sizes, int n_in,
                              void* d_out, int out_size)
{
    const float* pred   = (const float*)d_in[0];
    const float* target = (const float*)d_in[1];
    float* out = (float*)d_out;

    // dynamic smem: half2 slab + interleaved uint2 product buffer
    const int smem_bytes = HR*SH*(int)sizeof(unsigned int) + HR*SP2*(int)sizeof(uint2); // 50,232 B
    cudaFuncSetAttribute(wh_kernel, cudaFuncAttributeMaxDynamicSharedMemorySize, smem_bytes);

    dim3 g1(NTILE, DD, BB);   // 3200 blocks
    wh_kernel<<<g1, 256, smem_bytes>>>(pred, target);
    dpass_kernel<<<NBLK2, TPB2>>>();
    finalize_kernel<<<1, 256>>>(out);
}